// round 1
// baseline (speedup 1.0000x reference)
#include <cuda_runtime.h>
#include <math.h>

#define BB    8
#define NPG   4096
#define NN    32768
#define EE    262144
#define INC   1024
#define HID   512
#define NCLS  4
#define K1    2048
#define K2    1024

// ---------------- scratch (device globals; no allocations allowed) ----------
__device__ float g_t[NN * HID];     // GEMM output (pre-aggregation)
__device__ float g_h[NN * HID];     // layer activations
__device__ float g_dinv[NN];
__device__ float g_nmask[NN];
__device__ float g_rows[NN];        // per-row input scale for next GEMM
__device__ float g_sr[NN];
__device__ float g_so[NN];
__device__ float g_score[NN];
__device__ int   g_cnt[NN];
__device__ int   g_off[NN + 1];
__device__ int   g_cur[NN];
__device__ int   g_csr[EE];
__device__ float g_pool[BB * 2 * HID];
__device__ float g_fc1o[BB * HID];

__device__ __forceinline__ float lrelu(float x) { return x > 0.f ? x : 0.01f * x; }

// ---------------- graph preprocessing ---------------------------------------
__global__ void k_init() {
    int i = blockIdx.x * blockDim.x + threadIdx.x;
    if (i < NN) { g_cnt[i] = 0; g_nmask[i] = 1.f; g_rows[i] = 1.f; }
}

__global__ void k_count(const int* __restrict__ dst) {
    int e = blockIdx.x * blockDim.x + threadIdx.x;
    if (e < EE) atomicAdd(&g_cnt[dst[e]], 1);
}

__global__ void k_scan() {  // 1 block, 1024 threads, 32 counts each
    __shared__ int part[1024];
    int t = threadIdx.x;
    int base = t * 32;
    int s = 0;
#pragma unroll
    for (int i = 0; i < 32; i++) s += g_cnt[base + i];
    part[t] = s;
    __syncthreads();
    for (int off = 1; off < 1024; off <<= 1) {
        int v = (t >= off) ? part[t - off] : 0;
        __syncthreads();
        part[t] += v;
        __syncthreads();
    }
    int run = (t == 0) ? 0 : part[t - 1];
#pragma unroll
    for (int i = 0; i < 32; i++) {
        int c = g_cnt[base + i];
        g_off[base + i] = run;
        g_cur[base + i] = run;
        run += c;
    }
    if (t == 1023) g_off[NN] = run;
}

__global__ void k_scatter(const int* __restrict__ src, const int* __restrict__ dst) {
    int e = blockIdx.x * blockDim.x + threadIdx.x;
    if (e < EE) {
        int p = atomicAdd(&g_cur[dst[e]], 1);
        g_csr[p] = src[e];
    }
}

// ---------------- SGEMM: C[M,N] = (A * rowscale) @ W,  W is [K,N] ------------
// BM=BN=128, BK=8, 256 threads, 8x8 per-thread tile
__global__ void sgemm(const float* __restrict__ A, const float* __restrict__ W,
                      const float* __restrict__ rs, float* __restrict__ C,
                      int K, int Ndim) {
    __shared__ __align__(16) float As[8][128];
    __shared__ __align__(16) float Bs[8][128];
    int bm = blockIdx.y, bn = blockIdx.x;
    int tid = threadIdx.x;
    int tr = tid / 16, tc = tid % 16;

    float acc[8][8];
#pragma unroll
    for (int i = 0; i < 8; i++)
#pragma unroll
        for (int j = 0; j < 8; j++) acc[i][j] = 0.f;

    int arow = tid >> 1;
    int acol4 = (tid & 1) * 4;
    float rscale = rs[bm * 128 + arow];
    int brow = tid >> 5, bcol4 = (tid & 31) * 4;

    const float* Aptr = A + (size_t)(bm * 128 + arow) * K + acol4;
    const float* Wptr = W + (size_t)brow * Ndim + bn * 128 + bcol4;

    for (int k0 = 0; k0 < K; k0 += 8) {
        float4 a = *(const float4*)Aptr; Aptr += 8;
        As[acol4 + 0][arow] = a.x * rscale;
        As[acol4 + 1][arow] = a.y * rscale;
        As[acol4 + 2][arow] = a.z * rscale;
        As[acol4 + 3][arow] = a.w * rscale;
        float4 b = *(const float4*)Wptr; Wptr += (size_t)8 * Ndim;
        *(float4*)&Bs[brow][bcol4] = b;
        __syncthreads();
#pragma unroll
        for (int kk = 0; kk < 8; kk++) {
            float ar[8], br[8];
            *(float4*)&ar[0] = *(const float4*)&As[kk][tr * 8];
            *(float4*)&ar[4] = *(const float4*)&As[kk][tr * 8 + 4];
            *(float4*)&br[0] = *(const float4*)&Bs[kk][tc * 8];
            *(float4*)&br[4] = *(const float4*)&Bs[kk][tc * 8 + 4];
#pragma unroll
            for (int i = 0; i < 8; i++)
#pragma unroll
                for (int j = 0; j < 8; j++) acc[i][j] = fmaf(ar[i], br[j], acc[i][j]);
        }
        __syncthreads();
    }
    float* Cp = C + (size_t)(bm * 128 + tr * 8) * Ndim + bn * 128 + tc * 8;
#pragma unroll
    for (int i = 0; i < 8; i++) {
        *(float4*)(Cp + (size_t)i * Ndim)     = *(float4*)&acc[i][0];
        *(float4*)(Cp + (size_t)i * Ndim + 4) = *(float4*)&acc[i][4];
    }
}

// ---------------- GCN pieces -------------------------------------------------
__global__ void k_deg() {
    int v = blockIdx.x * blockDim.x + threadIdx.x;
    if (v >= NN) return;
    float nm = g_nmask[v];
    float s = 0.f;
    int e0 = g_off[v], e1 = g_off[v + 1];
    for (int i = e0; i < e1; i++) s += g_nmask[g_csr[i]];
    float deg = nm * (s + 1.f);
    g_dinv[v] = deg > 0.f ? rsqrtf(deg) : 0.f;
}

// out[v,c] = lrelu( dv*sum(ds*t[s,c]) + dv*dv*t[v,c] + bias[c] ),  128 threads x 4ch
__global__ void k_agg(const float* __restrict__ bias) {
    int v = blockIdx.x;
    int c = threadIdx.x;
    float dv = g_dinv[v];
    float a0 = 0.f, a1 = 0.f, a2 = 0.f, a3 = 0.f;
    int e0 = g_off[v], e1 = g_off[v + 1];
    for (int i = e0; i < e1; i++) {
        int s = g_csr[i];
        float ds = g_dinv[s];
        if (ds != 0.f) {
            const float* tr = g_t + (size_t)s * HID;
            a0 += ds * tr[c];
            a1 += ds * tr[c + 128];
            a2 += ds * tr[c + 256];
            a3 += ds * tr[c + 384];
        }
    }
    const float* tv = g_t + (size_t)v * HID;
    float dv2 = dv * dv;
    float* ho = g_h + (size_t)v * HID;
    ho[c]       = lrelu(dv * a0 + dv2 * tv[c]       + bias[c]);
    ho[c + 128] = lrelu(dv * a1 + dv2 * tv[c + 128] + bias[c + 128]);
    ho[c + 256] = lrelu(dv * a2 + dv2 * tv[c + 256] + bias[c + 256]);
    ho[c + 384] = lrelu(dv * a3 + dv2 * tv[c + 384] + bias[c + 384]);
}

// ---------------- SAGPool ----------------------------------------------------
__global__ void k_dots(const float* __restrict__ wr, const float* __restrict__ wo) {
    int warp = (blockIdx.x * blockDim.x + threadIdx.x) >> 5;
    int lane = threadIdx.x & 31;
    if (warp >= NN) return;
    const float* h = g_h + (size_t)warp * HID;
    float sr = 0.f, so = 0.f;
    for (int i = lane; i < HID; i += 32) {
        float hv = h[i];
        sr += hv * wr[i];
        so += hv * wo[i];
    }
#pragma unroll
    for (int o = 16; o > 0; o >>= 1) {
        sr += __shfl_down_sync(0xffffffff, sr, o);
        so += __shfl_down_sync(0xffffffff, so, o);
    }
    if (lane == 0) { g_sr[warp] = sr; g_so[warp] = so; }
}

__global__ void k_score(const float* __restrict__ br) {
    int v = blockIdx.x * blockDim.x + threadIdx.x;
    if (v >= NN) return;
    float nm = g_nmask[v];
    if (nm <= 0.f) { g_score[v] = -1e30f; return; }
    float s = 0.f;
    int e0 = g_off[v], e1 = g_off[v + 1];
    for (int i = e0; i < e1; i++) {
        int u = g_csr[i];
        s += g_nmask[u] * g_sr[u];
    }
    g_score[v] = s + br[0] + g_so[v];
}

// one block per graph: bitonic ascending sort of 4096 scores, threshold, keep
__global__ void k_topk(int kkeep) {
    __shared__ float v[NPG];
    int g = blockIdx.x, t = threadIdx.x;
    for (int i = t; i < NPG; i += 1024) v[i] = g_score[g * NPG + i];
    __syncthreads();
    for (int ksz = 2; ksz <= NPG; ksz <<= 1) {
        for (int j = ksz >> 1; j > 0; j >>= 1) {
            for (int i = t; i < NPG; i += 1024) {
                int ixj = i ^ j;
                if (ixj > i) {
                    bool up = ((i & ksz) == 0);
                    float a = v[i], b = v[ixj];
                    if (up ? (a > b) : (a < b)) { v[i] = b; v[ixj] = a; }
                }
            }
            __syncthreads();
        }
    }
    float T = v[NPG - kkeep];  // k-th largest
    for (int i = t; i < NPG; i += 1024) {
        int node = g * NPG + i;
        float sc = g_score[node];
        float keep = (sc >= T && g_nmask[node] > 0.f) ? 1.f : 0.f;
        g_nmask[node] = keep;
        g_rows[node] = keep * tanhf(sc);
    }
}

// ---------------- readout ----------------------------------------------------
__global__ void k_pool() {  // block per graph, 512 threads (one per channel)
    int g = blockIdx.x, c = threadIdx.x;
    float sum = 0.f, mx = -3.4e38f, cnt = 0.f;
    for (int n = 0; n < NPG; n++) {
        int node = g * NPG + n;
        if (g_nmask[node] > 0.f) {
            float h = g_h[(size_t)node * HID + c];
            sum += h;
            mx = fmaxf(mx, h);
            cnt += 1.f;
        }
    }
    g_pool[g * (2 * HID) + c]       = sum / cnt;
    g_pool[g * (2 * HID) + HID + c] = mx;
}

__global__ void k_fc1(const float* __restrict__ w, const float* __restrict__ b) {
    int g = blockIdx.x, o = threadIdx.x;
    const float* gp = g_pool + g * (2 * HID);
    float s = b[o];
    for (int k = 0; k < 2 * HID; k++) s = fmaf(gp[k], w[k * HID + o], s);
    g_fc1o[g * HID + o] = lrelu(s);
}

__global__ void k_fc2(const float* __restrict__ w, const float* __restrict__ b,
                      float* __restrict__ out) {
    int idx = threadIdx.x;  // 32 threads
    if (idx >= BB * NCLS) return;
    int g = idx / NCLS, c = idx % NCLS;
    const float* hv = g_fc1o + g * HID;
    float s = b[c];
    for (int k = 0; k < HID; k++) s = fmaf(hv[k], w[k * NCLS + c], s);
    out[idx] = s;
}

// ---------------- launch -----------------------------------------------------
extern "C" void kernel_launch(void* const* d_in, const int* in_sizes, int n_in,
                              void* d_out, int out_size) {
    const float* x     = (const float*)d_in[0];
    const int*   esrc  = (const int*)d_in[1];
    const int*   edst  = (const int*)d_in[2];
    const float* W1    = (const float*)d_in[3];
    const float* b1    = (const float*)d_in[4];
    const float* p1wr  = (const float*)d_in[5];
    const float* p1br  = (const float*)d_in[6];
    const float* p1wo  = (const float*)d_in[7];
    const float* W2    = (const float*)d_in[8];
    const float* b2    = (const float*)d_in[9];
    const float* p2wr  = (const float*)d_in[10];
    const float* p2br  = (const float*)d_in[11];
    const float* p2wo  = (const float*)d_in[12];
    const float* W3    = (const float*)d_in[13];
    const float* b3    = (const float*)d_in[14];
    const float* fc1w  = (const float*)d_in[15];
    const float* fc1b  = (const float*)d_in[16];
    const float* fc2w  = (const float*)d_in[17];
    const float* fc2b  = (const float*)d_in[18];
    float* out = (float*)d_out;

    float* dT;   cudaGetSymbolAddress((void**)&dT, g_t);
    float* dH;   cudaGetSymbolAddress((void**)&dH, g_h);
    float* dRS;  cudaGetSymbolAddress((void**)&dRS, g_rows);

    // graph preprocessing (edges are static per launch, rebuilt for determinism)
    k_init<<<NN / 256, 256>>>();
    k_count<<<EE / 256, 256>>>(edst);
    k_scan<<<1, 1024>>>();
    k_scatter<<<EE / 256, 256>>>(esrc, edst);

    // ---- layer 1 ----
    sgemm<<<dim3(HID / 128, NN / 128), 256>>>(x, W1, dRS, dT, INC, HID);
    k_deg<<<NN / 256, 256>>>();
    k_agg<<<NN, 128>>>(b1);
    // pool 1
    k_dots<<<NN / 8, 256>>>(p1wr, p1wo);
    k_score<<<NN / 256, 256>>>(p1br);
    k_topk<<<BB, 1024>>>(K1);

    // ---- layer 2 ----
    sgemm<<<dim3(HID / 128, NN / 128), 256>>>(dH, W2, dRS, dT, HID, HID);
    k_deg<<<NN / 256, 256>>>();
    k_agg<<<NN, 128>>>(b2);
    // pool 2
    k_dots<<<NN / 8, 256>>>(p2wr, p2wo);
    k_score<<<NN / 256, 256>>>(p2br);
    k_topk<<<BB, 1024>>>(K2);

    // ---- layer 3 ----
    sgemm<<<dim3(HID / 128, NN / 128), 256>>>(dH, W3, dRS, dT, HID, HID);
    k_deg<<<NN / 256, 256>>>();
    k_agg<<<NN, 128>>>(b3);

    // ---- readout ----
    k_pool<<<BB, HID>>>();
    k_fc1<<<BB, HID>>>(fc1w, fc1b);
    k_fc2<<<1, 32>>>(fc2w, fc2b, out);
}

// round 3
// speedup vs baseline: 1.7262x; 1.7262x over previous
#include <cuda_runtime.h>
#include <math.h>
#include <stdint.h>

#define BB    8
#define NPG   4096
#define NN    32768
#define EE    262144
#define INC   1024
#define HID   512
#define NCLS  4
#define K1    2048
#define K2    1024
#define NACT2 (BB*K1)   /* 16384 rows active in layer 2 */
#define NACT3 (BB*K2)   /* 8192 rows active in layer 3  */

// ---------------- scratch (device globals; no allocations allowed) ----------
__device__ float g_t[NN * HID];     // GEMM output (pre-aggregation)
__device__ float g_h[NN * HID];     // layer activations
__device__ float g_dinv[NN];
__device__ float g_nmask[NN];
__device__ float g_rows[NN];        // per-row input scale for next GEMM
__device__ float g_sr[NN];
__device__ float g_so[NN];
__device__ float g_score[NN];
__device__ int   g_cnt[NN];
__device__ int   g_off[NN + 1];
__device__ int   g_cur[NN];
__device__ int   g_csr[EE];
__device__ float g_pool[BB * 2 * HID];
__device__ float g_fc1o[BB * HID];
__device__ float g_w1t_hi[HID * INC];   // W1^T [N,K] tf32-hi
__device__ float g_w1t_lo[HID * INC];
__device__ float g_w2t_hi[HID * HID];
__device__ float g_w2t_lo[HID * HID];
__device__ float g_w3t_hi[HID * HID];
__device__ float g_w3t_lo[HID * HID];
__device__ int   g_iota[NN];
__device__ int   g_ridx2[NACT2];
__device__ int   g_ridx3[NACT3];
__device__ int   g_ctr2;
__device__ int   g_ctr3;

__device__ __forceinline__ float lrelu(float x) { return x > 0.f ? x : 0.01f * x; }

// ---------------- tf32 helpers (base-target PTX, sm_80+) --------------------
__device__ __forceinline__ float totf(float v) {
    uint32_t u;
    asm("cvt.rna.tf32.f32 %0, %1;" : "=r"(u) : "f"(v));
    return __uint_as_float(u);
}
__device__ __forceinline__ uint32_t f2u(float v) { return __float_as_uint(v); }

__device__ __forceinline__ void mma8(float* c, const uint32_t* a, const uint32_t* b) {
    asm volatile(
        "mma.sync.aligned.m16n8k8.row.col.f32.tf32.tf32.f32 "
        "{%0,%1,%2,%3}, {%4,%5,%6,%7}, {%8,%9}, {%0,%1,%2,%3};"
        : "+f"(c[0]), "+f"(c[1]), "+f"(c[2]), "+f"(c[3])
        : "r"(a[0]), "r"(a[1]), "r"(a[2]), "r"(a[3]), "r"(b[0]), "r"(b[1]));
}

// ======= tf32x3 HMMA GEMM: C[ridx[m], nb*128+n] = (A[ridx]*rs) @ B^T ========
// B given pre-transposed+split: Bhi/Blo are [Ntot][K] row-major.
// block 128x128, BK=32, 256 thr, 8 warps = 4(M) x 2(N), warp tile 32x64.
#define PAD 36
#define STG_MAT 4608   /* 128*36 floats per matrix per stage */
#define SM_BYTES ((256 + 8 * STG_MAT) * 4)   /* 148480 */

__global__ void __launch_bounds__(256, 1)
mma_gemm(const float* __restrict__ A, const float* __restrict__ Bhi,
         const float* __restrict__ Blo, const float* __restrict__ rs,
         const int* __restrict__ ridx, float* __restrict__ C, int K)
{
    extern __shared__ float smf[];
    int*   ridx_s = (int*)smf;          // 128
    float* rs_s   = smf + 128;          // 128
    float* stg    = smf + 256;          // 2 stages x 4 mats x 4608

    int tid = threadIdx.x;
    int lane = tid & 31, wid = tid >> 5;
    int g = lane >> 2, tg = lane & 3;
    int wm = wid & 3, wn = wid >> 2;
    int nb = blockIdx.x, mb = blockIdx.y;

    if (tid < 128) {
        int r = ridx[mb * 128 + tid];
        ridx_s[tid] = r;
        rs_s[tid] = rs[r];
    }
    __syncthreads();

    float acc[2][8][4];
#pragma unroll
    for (int a = 0; a < 2; a++)
#pragma unroll
        for (int b = 0; b < 8; b++)
#pragma unroll
            for (int q = 0; q < 4; q++) acc[a][b][q] = 0.f;

    int jm[4], jc[4];
#pragma unroll
    for (int i = 0; i < 4; i++) { int j = tid + 256 * i; jm[i] = j >> 3; jc[i] = (j & 7) * 4; }

    float4 sa[4], sbh[4], sbl[4];

    auto do_ldg = [&](int it) {
        int kb = it * 32;
#pragma unroll
        for (int i = 0; i < 4; i++) {
            sa[i]  = *(const float4*)(A   + (size_t)ridx_s[jm[i]] * K       + kb + jc[i]);
            sbh[i] = *(const float4*)(Bhi + (size_t)(nb * 128 + jm[i]) * K + kb + jc[i]);
            sbl[i] = *(const float4*)(Blo + (size_t)(nb * 128 + jm[i]) * K + kb + jc[i]);
        }
    };

    auto do_sts = [&](int s) {
        float* Ah = stg + (s * 4 + 0) * STG_MAT;
        float* Al = stg + (s * 4 + 1) * STG_MAT;
        float* Bh = stg + (s * 4 + 2) * STG_MAT;
        float* Bl = stg + (s * 4 + 3) * STG_MAT;
#pragma unroll
        for (int i = 0; i < 4; i++) {
            int m = jm[i], c = jc[i];
            float rsc = rs_s[m];
            float v0 = sa[i].x * rsc, v1 = sa[i].y * rsc, v2 = sa[i].z * rsc, v3 = sa[i].w * rsc;
            float h0 = totf(v0), h1 = totf(v1), h2 = totf(v2), h3 = totf(v3);
            int o = m * PAD + c;
            Ah[o] = h0; Ah[o + 1] = h1; Ah[o + 2] = h2; Ah[o + 3] = h3;
            Al[o] = totf(v0 - h0); Al[o + 1] = totf(v1 - h1);
            Al[o + 2] = totf(v2 - h2); Al[o + 3] = totf(v3 - h3);
            *(float4*)&Bh[o] = sbh[i];
            *(float4*)&Bl[o] = sbl[i];
        }
    };

    auto do_comp = [&](int s) {
        const float* Ah = stg + (s * 4 + 0) * STG_MAT;
        const float* Al = stg + (s * 4 + 1) * STG_MAT;
        const float* Bh = stg + (s * 4 + 2) * STG_MAT;
        const float* Bl = stg + (s * 4 + 3) * STG_MAT;
#pragma unroll
        for (int k8 = 0; k8 < 4; k8++) {
            int kk = k8 * 8 + tg;
            uint32_t ah[2][4], al[2][4];
#pragma unroll
            for (int tm = 0; tm < 2; tm++) {
                int r0 = (wm * 32 + tm * 16 + g) * PAD;
                ah[tm][0] = f2u(Ah[r0 + kk]);
                ah[tm][1] = f2u(Ah[r0 + 8 * PAD + kk]);
                ah[tm][2] = f2u(Ah[r0 + kk + 4]);
                ah[tm][3] = f2u(Ah[r0 + 8 * PAD + kk + 4]);
                al[tm][0] = f2u(Al[r0 + kk]);
                al[tm][1] = f2u(Al[r0 + 8 * PAD + kk]);
                al[tm][2] = f2u(Al[r0 + kk + 4]);
                al[tm][3] = f2u(Al[r0 + 8 * PAD + kk + 4]);
            }
#pragma unroll
            for (int tn = 0; tn < 8; tn++) {
                int n0 = (wn * 64 + tn * 8 + g) * PAD;
                uint32_t bh[2] = { f2u(Bh[n0 + kk]), f2u(Bh[n0 + kk + 4]) };
                uint32_t bl[2] = { f2u(Bl[n0 + kk]), f2u(Bl[n0 + kk + 4]) };
#pragma unroll
                for (int tm = 0; tm < 2; tm++) {
                    mma8(acc[tm][tn], ah[tm], bh);
                    mma8(acc[tm][tn], al[tm], bh);
                    mma8(acc[tm][tn], ah[tm], bl);
                }
            }
        }
    };

    const int NIT = K >> 5;
    do_ldg(0);
    do_sts(0);
    __syncthreads();
    for (int it = 0; it < NIT; it++) {
        if (it + 1 < NIT) do_ldg(it + 1);
        do_comp(it & 1);
        __syncthreads();
        if (it + 1 < NIT) {
            do_sts((it + 1) & 1);
            __syncthreads();
        }
    }

    // epilogue: scatter C rows
#pragma unroll
    for (int tm = 0; tm < 2; tm++) {
        int r0 = wm * 32 + tm * 16 + g;
        size_t o0 = (size_t)ridx_s[r0] * HID;
        size_t o1 = (size_t)ridx_s[r0 + 8] * HID;
#pragma unroll
        for (int tn = 0; tn < 8; tn++) {
            int n0 = nb * 128 + wn * 64 + tn * 8 + 2 * tg;
            *(float2*)(C + o0 + n0) = make_float2(acc[tm][tn][0], acc[tm][tn][1]);
            *(float2*)(C + o1 + n0) = make_float2(acc[tm][tn][2], acc[tm][tn][3]);
        }
    }
}

// ---- one-time prep: transpose + tf32-split W [K][N] -> hi/lo [N][K] --------
__global__ void k_wsplit(const float* __restrict__ W, float* __restrict__ hi,
                         float* __restrict__ lo, int K, int N) {
    int idx = blockIdx.x * blockDim.x + threadIdx.x;
    if (idx >= N * K) return;
    int n = idx / K, k = idx % K;
    float v = W[(size_t)k * N + n];
    float h = totf(v);
    hi[idx] = h;
    lo[idx] = totf(v - h);
}

// ---------------- graph preprocessing ---------------------------------------
__global__ void k_init() {
    int i = blockIdx.x * blockDim.x + threadIdx.x;
    if (i < NN) { g_cnt[i] = 0; g_nmask[i] = 1.f; g_rows[i] = 1.f; g_iota[i] = i; }
    if (i == 0) { g_ctr2 = 0; g_ctr3 = 0; }
}

__global__ void k_count(const int* __restrict__ dst) {
    int e = blockIdx.x * blockDim.x + threadIdx.x;
    if (e < EE) atomicAdd(&g_cnt[dst[e]], 1);
}

__global__ void k_scan() {
    __shared__ int part[1024];
    int t = threadIdx.x;
    int base = t * 32;
    int s = 0;
#pragma unroll
    for (int i = 0; i < 32; i++) s += g_cnt[base + i];
    part[t] = s;
    __syncthreads();
    for (int off = 1; off < 1024; off <<= 1) {
        int v = (t >= off) ? part[t - off] : 0;
        __syncthreads();
        part[t] += v;
        __syncthreads();
    }
    int run = (t == 0) ? 0 : part[t - 1];
#pragma unroll
    for (int i = 0; i < 32; i++) {
        int c = g_cnt[base + i];
        g_off[base + i] = run;
        g_cur[base + i] = run;
        run += c;
    }
    if (t == 1023) g_off[NN] = run;
}

__global__ void k_scatter(const int* __restrict__ src, const int* __restrict__ dst) {
    int e = blockIdx.x * blockDim.x + threadIdx.x;
    if (e < EE) {
        int p = atomicAdd(&g_cur[dst[e]], 1);
        g_csr[p] = src[e];
    }
}

__global__ void k_compact(int* __restrict__ ridx, int* __restrict__ ctr) {
    int v = blockIdx.x * blockDim.x + threadIdx.x;
    if (v < NN && g_nmask[v] > 0.f) {
        int p = atomicAdd(ctr, 1);
        ridx[p] = v;
    }
}

// ---------------- GCN pieces -------------------------------------------------
__global__ void k_deg() {
    int v = blockIdx.x * blockDim.x + threadIdx.x;
    if (v >= NN) return;
    float nm = g_nmask[v];
    if (nm <= 0.f) { g_dinv[v] = 0.f; return; }
    float s = 0.f;
    int e0 = g_off[v], e1 = g_off[v + 1];
    for (int i = e0; i < e1; i++) s += g_nmask[g_csr[i]];
    g_dinv[v] = rsqrtf(s + 1.f);
}

__global__ void k_agg(const float* __restrict__ bias) {
    int v = blockIdx.x;
    int c = threadIdx.x;
    float dv = g_dinv[v];
    if (dv == 0.f) return;
    float a0 = 0.f, a1 = 0.f, a2 = 0.f, a3 = 0.f;
    int e0 = g_off[v], e1 = g_off[v + 1];
    for (int i = e0; i < e1; i++) {
        int s = g_csr[i];
        float ds = g_dinv[s];
        if (ds != 0.f) {
            const float* tr = g_t + (size_t)s * HID;
            a0 += ds * tr[c];
            a1 += ds * tr[c + 128];
            a2 += ds * tr[c + 256];
            a3 += ds * tr[c + 384];
        }
    }
    const float* tv = g_t + (size_t)v * HID;
    float dv2 = dv * dv;
    float* ho = g_h + (size_t)v * HID;
    ho[c]       = lrelu(dv * a0 + dv2 * tv[c]       + bias[c]);
    ho[c + 128] = lrelu(dv * a1 + dv2 * tv[c + 128] + bias[c + 128]);
    ho[c + 256] = lrelu(dv * a2 + dv2 * tv[c + 256] + bias[c + 256]);
    ho[c + 384] = lrelu(dv * a3 + dv2 * tv[c + 384] + bias[c + 384]);
}

// ---------------- SAGPool ----------------------------------------------------
__global__ void k_dots(const float* __restrict__ wr, const float* __restrict__ wo) {
    int warp = (blockIdx.x * blockDim.x + threadIdx.x) >> 5;
    int lane = threadIdx.x & 31;
    if (warp >= NN) return;
    if (g_nmask[warp] <= 0.f) {
        if (lane == 0) { g_sr[warp] = 0.f; g_so[warp] = 0.f; }
        return;
    }
    const float* h = g_h + (size_t)warp * HID;
    float sr = 0.f, so = 0.f;
    for (int i = lane; i < HID; i += 32) {
        float hv = h[i];
        sr += hv * wr[i];
        so += hv * wo[i];
    }
#pragma unroll
    for (int o = 16; o > 0; o >>= 1) {
        sr += __shfl_down_sync(0xffffffff, sr, o);
        so += __shfl_down_sync(0xffffffff, so, o);
    }
    if (lane == 0) { g_sr[warp] = sr; g_so[warp] = so; }
}

__global__ void k_score(const float* __restrict__ br) {
    int v = blockIdx.x * blockDim.x + threadIdx.x;
    if (v >= NN) return;
    if (g_nmask[v] <= 0.f) { g_score[v] = -1e30f; return; }
    float s = 0.f;
    int e0 = g_off[v], e1 = g_off[v + 1];
    for (int i = e0; i < e1; i++) {
        int u = g_csr[i];
        s += g_nmask[u] * g_sr[u];
    }
    g_score[v] = s + br[0] + g_so[v];
}

__global__ void k_topk(int kkeep) {
    __shared__ float v[NPG];
    int g = blockIdx.x, t = threadIdx.x;
    for (int i = t; i < NPG; i += 1024) v[i] = g_score[g * NPG + i];
    __syncthreads();
    for (int ksz = 2; ksz <= NPG; ksz <<= 1) {
        for (int j = ksz >> 1; j > 0; j >>= 1) {
            for (int i = t; i < NPG; i += 1024) {
                int ixj = i ^ j;
                if (ixj > i) {
                    bool up = ((i & ksz) == 0);
                    float a = v[i], b = v[ixj];
                    if (up ? (a > b) : (a < b)) { v[i] = b; v[ixj] = a; }
                }
            }
            __syncthreads();
        }
    }
    float T = v[NPG - kkeep];
    for (int i = t; i < NPG; i += 1024) {
        int node = g * NPG + i;
        float sc = g_score[node];
        float keep = (sc >= T && g_nmask[node] > 0.f) ? 1.f : 0.f;
        g_nmask[node] = keep;
        g_rows[node] = keep * tanhf(sc);
    }
}

// ---------------- readout ----------------------------------------------------
__global__ void k_pool() {
    int g = blockIdx.x, c = threadIdx.x;
    float sum = 0.f, mx = -3.4e38f, cnt = 0.f;
    for (int n = 0; n < NPG; n++) {
        int node = g * NPG + n;
        if (g_nmask[node] > 0.f) {
            float h = g_h[(size_t)node * HID + c];
            sum += h;
            mx = fmaxf(mx, h);
            cnt += 1.f;
        }
    }
    g_pool[g * (2 * HID) + c]       = sum / cnt;
    g_pool[g * (2 * HID) + HID + c] = mx;
}

__global__ void k_fc1(const float* __restrict__ w, const float* __restrict__ b) {
    int g = blockIdx.x, o = threadIdx.x;
    const float* gp = g_pool + g * (2 * HID);
    float s = b[o];
    for (int k = 0; k < 2 * HID; k++) s = fmaf(gp[k], w[k * HID + o], s);
    g_fc1o[g * HID + o] = lrelu(s);
}

__global__ void k_fc2(const float* __restrict__ w, const float* __restrict__ b,
                      float* __restrict__ out) {
    int idx = threadIdx.x;
    if (idx >= BB * NCLS) return;
    int g = idx / NCLS, c = idx % NCLS;
    const float* hv = g_fc1o + g * HID;
    float s = b[c];
    for (int k = 0; k < HID; k++) s = fmaf(hv[k], w[k * NCLS + c], s);
    out[idx] = s;
}

// ---------------- launch -----------------------------------------------------
extern "C" void kernel_launch(void* const* d_in, const int* in_sizes, int n_in,
                              void* d_out, int out_size) {
    const float* x     = (const float*)d_in[0];
    const int*   esrc  = (const int*)d_in[1];
    const int*   edst  = (const int*)d_in[2];
    const float* W1    = (const float*)d_in[3];
    const float* b1    = (const float*)d_in[4];
    const float* p1wr  = (const float*)d_in[5];
    const float* p1br  = (const float*)d_in[6];
    const float* p1wo  = (const float*)d_in[7];
    const float* W2    = (const float*)d_in[8];
    const float* b2    = (const float*)d_in[9];
    const float* p2wr  = (const float*)d_in[10];
    const float* p2br  = (const float*)d_in[11];
    const float* p2wo  = (const float*)d_in[12];
    const float* W3    = (const float*)d_in[13];
    const float* b3    = (const float*)d_in[14];
    const float* fc1w  = (const float*)d_in[15];
    const float* fc1b  = (const float*)d_in[16];
    const float* fc2w  = (const float*)d_in[17];
    const float* fc2b  = (const float*)d_in[18];
    float* out = (float*)d_out;

    float* dT;     cudaGetSymbolAddress((void**)&dT, g_t);
    float* dH;     cudaGetSymbolAddress((void**)&dH, g_h);
    float* dRS;    cudaGetSymbolAddress((void**)&dRS, g_rows);
    float* dW1hi;  cudaGetSymbolAddress((void**)&dW1hi, g_w1t_hi);
    float* dW1lo;  cudaGetSymbolAddress((void**)&dW1lo, g_w1t_lo);
    float* dW2hi;  cudaGetSymbolAddress((void**)&dW2hi, g_w2t_hi);
    float* dW2lo;  cudaGetSymbolAddress((void**)&dW2lo, g_w2t_lo);
    float* dW3hi;  cudaGetSymbolAddress((void**)&dW3hi, g_w3t_hi);
    float* dW3lo;  cudaGetSymbolAddress((void**)&dW3lo, g_w3t_lo);
    int*   dIota;  cudaGetSymbolAddress((void**)&dIota, g_iota);
    int*   dR2;    cudaGetSymbolAddress((void**)&dR2, g_ridx2);
    int*   dR3;    cudaGetSymbolAddress((void**)&dR3, g_ridx3);
    int*   dC2;    cudaGetSymbolAddress((void**)&dC2, g_ctr2);
    int*   dC3;    cudaGetSymbolAddress((void**)&dC3, g_ctr3);

    static int cfg_done = 0;
    if (!cfg_done) {   // runs on the (pre-capture) correctness call; config-only
        cudaFuncSetAttribute(mma_gemm, cudaFuncAttributeMaxDynamicSharedMemorySize, SM_BYTES);
        cfg_done = 1;
    }

    // preprocessing
    k_init<<<NN / 256, 256>>>();
    k_count<<<EE / 256, 256>>>(edst);
    k_scan<<<1, 1024>>>();
    k_scatter<<<EE / 256, 256>>>(esrc, edst);
    k_wsplit<<<(HID * INC) / 256, 256>>>(W1, dW1hi, dW1lo, INC, HID);
    k_wsplit<<<(HID * HID) / 256, 256>>>(W2, dW2hi, dW2lo, HID, HID);
    k_wsplit<<<(HID * HID) / 256, 256>>>(W3, dW3hi, dW3lo, HID, HID);

    // ---- layer 1: tf32x3 HMMA GEMM over all rows ----
    mma_gemm<<<dim3(HID / 128, NN / 128), 256, SM_BYTES>>>(x, dW1hi, dW1lo, dRS, dIota, dT, INC);
    k_deg<<<NN / 256, 256>>>();
    k_agg<<<NN, 128>>>(b1);
    k_dots<<<NN / 8, 256>>>(p1wr, p1wo);
    k_score<<<NN / 256, 256>>>(p1br);
    k_topk<<<BB, 1024>>>(K1);
    k_compact<<<NN / 256, 256>>>(dR2, dC2);

    // ---- layer 2: HMMA GEMM on 16384 active rows ----
    mma_gemm<<<dim3(HID / 128, NACT2 / 128), 256, SM_BYTES>>>(dH, dW2hi, dW2lo, dRS, dR2, dT, HID);
    k_deg<<<NN / 256, 256>>>();
    k_agg<<<NN, 128>>>(b2);
    k_dots<<<NN / 8, 256>>>(p2wr, p2wo);
    k_score<<<NN / 256, 256>>>(p2br);
    k_topk<<<BB, 1024>>>(K2);
    k_compact<<<NN / 256, 256>>>(dR3, dC3);

    // ---- layer 3: HMMA GEMM on 8192 active rows ----
    mma_gemm<<<dim3(HID / 128, NACT3 / 128), 256, SM_BYTES>>>(dH, dW3hi, dW3lo, dRS, dR3, dT, HID);
    k_deg<<<NN / 256, 256>>>();
    k_agg<<<NN, 128>>>(b3);

    // ---- readout ----
    k_pool<<<BB, HID>>>();
    k_fc1<<<BB, HID>>>(fc1w, fc1b);
    k_fc2<<<1, 32>>>(fc2w, fc2b, out);
}

// round 4
// speedup vs baseline: 2.1613x; 1.2520x over previous
#include <cuda_runtime.h>
#include <math.h>
#include <stdint.h>

#define BB    8
#define NPG   4096
#define NN    32768
#define EE    262144
#define INC   1024
#define HID   512
#define NCLS  4
#define K1    2048
#define K2    1024
#define NACT2 (BB*K1)
#define NACT3 (BB*K2)

// ---------------- scratch (device globals; no allocations allowed) ----------
__device__ float g_t[NN * HID];
__device__ float g_h[NN * HID];
__device__ float g_dinv[NN];
__device__ float g_nmask[NN];
__device__ float g_rows[NN];
__device__ float g_sr[NN];
__device__ float g_so[NN];
__device__ float g_score[NN];
__device__ int   g_cnt[NN];
__device__ int   g_off[NN + 1];
__device__ int   g_cur[NN];
__device__ int   g_csr[EE];
__device__ float g_pool[BB * 2 * HID];
__device__ float g_fc1o[BB * HID];
__device__ float g_w1t_hi[HID * INC];
__device__ float g_w1t_lo[HID * INC];
__device__ float g_w2t_hi[HID * HID];
__device__ float g_w2t_lo[HID * HID];
__device__ float g_w3t_hi[HID * HID];
__device__ float g_w3t_lo[HID * HID];
__device__ int   g_iota[NN];
__device__ int   g_ridx2[NACT2];
__device__ int   g_ridx3[NACT3];
__device__ int   g_ctr2;
__device__ int   g_ctr3;
__device__ float g_pp_sum[BB * 16 * HID];
__device__ float g_pp_max[BB * 16 * HID];
__device__ float g_pp_cnt[BB * 16];

__device__ __forceinline__ float lrelu(float x) { return x > 0.f ? x : 0.01f * x; }

// ---------------- tf32 helpers (base-target PTX, sm_80+) --------------------
__device__ __forceinline__ float totf(float v) {
    uint32_t u;
    asm("cvt.rna.tf32.f32 %0, %1;" : "=r"(u) : "f"(v));
    return __uint_as_float(u);
}
__device__ __forceinline__ uint32_t f2u(float v) { return __float_as_uint(v); }

__device__ __forceinline__ void mma8(float* c, const uint32_t* a, const uint32_t* b) {
    asm volatile(
        "mma.sync.aligned.m16n8k8.row.col.f32.tf32.tf32.f32 "
        "{%0,%1,%2,%3}, {%4,%5,%6,%7}, {%8,%9}, {%0,%1,%2,%3};"
        : "+f"(c[0]), "+f"(c[1]), "+f"(c[2]), "+f"(c[3])
        : "r"(a[0]), "r"(a[1]), "r"(a[2]), "r"(b[0]), "r"(b[1]), "r"(a[3]));
}
// NOTE: constraint order must match %4..%9 usage; use explicit correct version:
__device__ __forceinline__ void mma8v(float* c, const uint32_t* a, const uint32_t* b) {
    asm volatile(
        "mma.sync.aligned.m16n8k8.row.col.f32.tf32.tf32.f32 "
        "{%0,%1,%2,%3}, {%4,%5,%6,%7}, {%8,%9}, {%0,%1,%2,%3};"
        : "+f"(c[0]), "+f"(c[1]), "+f"(c[2]), "+f"(c[3])
        : "r"(a[0]), "r"(a[1]), "r"(a[2]), "r"(a[3]), "r"(b[0]), "r"(b[1]));
}

// ======= tf32x3 HMMA GEMM, fragment-permuted smem ==========================
// block 128x128, BK=32, 256 thr, 8 warps = 4(M) x 2(N), warp tile 32x64.
// A stored as m16n8k8 fragments: Ah[m16][k8][lane^k8][slot0..3] -> LDS.128
// B stored as fragment pairs:    Bh[n8][k8][lane^k8][slot0..1] -> LDS.64
#define STG_FLOATS 16384                      /* 4 mats x 4096 per stage */
#define SM_BYTES ((256 + 2 * STG_FLOATS) * 4) /* 132 KB */

__global__ void __launch_bounds__(256, 1)
mma_gemm(const float* __restrict__ A, const float* __restrict__ Bhi,
         const float* __restrict__ Blo, const float* __restrict__ rs,
         const int* __restrict__ ridx, float* __restrict__ C, int K)
{
    extern __shared__ float smf[];
    int*   ridx_s = (int*)smf;
    float* rs_s   = smf + 128;
    float* stg    = smf + 256;

    int tid = threadIdx.x;
    int lane = tid & 31, wid = tid >> 5;
    int g = lane >> 2, tg = lane & 3;
    int wm = wid & 3, wn = wid >> 2;
    int nb = blockIdx.x, mb = blockIdx.y;

    if (tid < 128) {
        int r = ridx[mb * 128 + tid];
        ridx_s[tid] = r;
        rs_s[tid] = rs[r];
    }
    __syncthreads();

    float acc[2][8][4];
#pragma unroll
    for (int a = 0; a < 2; a++)
#pragma unroll
        for (int b = 0; b < 8; b++)
#pragma unroll
            for (int q = 0; q < 4; q++) acc[a][b][q] = 0.f;

    // loader geometry: j = tid + 256*i covers 128 rows x 8 k-quads
    int jm[4], jc[4];
    const float *pa[4], *pbh[4], *pbl[4];
    float rsc[4];
#pragma unroll
    for (int i = 0; i < 4; i++) {
        int j = tid + 256 * i;
        jm[i] = j >> 3; jc[i] = (j & 7) * 4;
        pa[i]  = A   + (size_t)ridx_s[jm[i]] * K + jc[i];
        pbh[i] = Bhi + (size_t)(nb * 128 + jm[i]) * K + jc[i];
        pbl[i] = Blo + (size_t)(nb * 128 + jm[i]) * K + jc[i];
        rsc[i] = rs_s[jm[i]];
    }

    float4 sa[4], sbh[4], sbl[4];

    auto do_ldg = [&]() {
#pragma unroll
        for (int i = 0; i < 4; i++) {
            sa[i]  = *(const float4*)pa[i];  pa[i]  += 32;
            sbh[i] = *(const float4*)pbh[i]; pbh[i] += 32;
            sbl[i] = *(const float4*)pbl[i]; pbl[i] += 32;
        }
    };

    auto do_sts = [&](int s) {
        float* Ah = stg + s * STG_FLOATS;
        float* Al = Ah + 4096;
        float* Bh = Ah + 8192;
        float* Bl = Ah + 12288;
#pragma unroll
        for (int i = 0; i < 4; i++) {
            int m = jm[i], kq = jc[i];
            int k8 = kq >> 3, half = (kq >> 2) & 1;
            // ---- A fragment store ----
            int m16 = m >> 4, r = m & 15, ga = r & 7, rb = r >> 3;
            int slotA = half * 2 + rb;
            int baseA = m16 * 512 + k8 * 128 + slotA;
            float v0 = sa[i].x * rsc[i], v1 = sa[i].y * rsc[i];
            float v2 = sa[i].z * rsc[i], v3 = sa[i].w * rsc[i];
            float h0 = totf(v0), h1 = totf(v1), h2 = totf(v2), h3 = totf(v3);
            int l0 = ((ga * 4 + 0) ^ k8) * 4, l1 = ((ga * 4 + 1) ^ k8) * 4;
            int l2 = ((ga * 4 + 2) ^ k8) * 4, l3 = ((ga * 4 + 3) ^ k8) * 4;
            Ah[baseA + l0] = h0; Ah[baseA + l1] = h1;
            Ah[baseA + l2] = h2; Ah[baseA + l3] = h3;
            Al[baseA + l0] = totf(v0 - h0); Al[baseA + l1] = totf(v1 - h1);
            Al[baseA + l2] = totf(v2 - h2); Al[baseA + l3] = totf(v3 - h3);
            // ---- B fragment store ----
            int n8 = m >> 3, gb = m & 7;
            int baseB = n8 * 256 + k8 * 64 + half;
            int b0 = ((gb * 4 + 0) ^ k8) * 2, b1 = ((gb * 4 + 1) ^ k8) * 2;
            int b2 = ((gb * 4 + 2) ^ k8) * 2, b3 = ((gb * 4 + 3) ^ k8) * 2;
            Bh[baseB + b0] = sbh[i].x; Bh[baseB + b1] = sbh[i].y;
            Bh[baseB + b2] = sbh[i].z; Bh[baseB + b3] = sbh[i].w;
            Bl[baseB + b0] = sbl[i].x; Bl[baseB + b1] = sbl[i].y;
            Bl[baseB + b2] = sbl[i].z; Bl[baseB + b3] = sbl[i].w;
        }
    };

    auto do_comp = [&](int s) {
        const float* Ah = stg + s * STG_FLOATS;
        const float* Al = Ah + 4096;
        const float* Bh = Ah + 8192;
        const float* Bl = Ah + 12288;
#pragma unroll
        for (int k8 = 0; k8 < 4; k8++) {
            int lx = (lane ^ k8);
            uint32_t ah[2][4], al[2][4];
#pragma unroll
            for (int tm = 0; tm < 2; tm++) {
                int m16 = wm * 2 + tm;
                float4 fh = *(const float4*)&Ah[m16 * 512 + k8 * 128 + lx * 4];
                float4 fl = *(const float4*)&Al[m16 * 512 + k8 * 128 + lx * 4];
                ah[tm][0] = f2u(fh.x); ah[tm][1] = f2u(fh.y);
                ah[tm][2] = f2u(fh.z); ah[tm][3] = f2u(fh.w);
                al[tm][0] = f2u(fl.x); al[tm][1] = f2u(fl.y);
                al[tm][2] = f2u(fl.z); al[tm][3] = f2u(fl.w);
            }
#pragma unroll
            for (int tn = 0; tn < 8; tn++) {
                int n8 = wn * 8 + tn;
                float2 gh = *(const float2*)&Bh[n8 * 256 + k8 * 64 + lx * 2];
                float2 gl = *(const float2*)&Bl[n8 * 256 + k8 * 64 + lx * 2];
                uint32_t bh[2] = { f2u(gh.x), f2u(gh.y) };
                uint32_t bl[2] = { f2u(gl.x), f2u(gl.y) };
#pragma unroll
                for (int tm = 0; tm < 2; tm++) {
                    mma8v(acc[tm][tn], ah[tm], bh);
                    mma8v(acc[tm][tn], al[tm], bh);
                    mma8v(acc[tm][tn], ah[tm], bl);
                }
            }
        }
    };

    const int NIT = K >> 5;
    do_ldg();
    do_sts(0);
    __syncthreads();
    for (int it = 0; it < NIT; it++) {
        if (it + 1 < NIT) do_ldg();
        do_comp(it & 1);
        if (it + 1 < NIT) do_sts((it + 1) & 1);
        __syncthreads();
    }

#pragma unroll
    for (int tm = 0; tm < 2; tm++) {
        int r0 = wm * 32 + tm * 16 + g;
        size_t o0 = (size_t)ridx_s[r0] * HID;
        size_t o1 = (size_t)ridx_s[r0 + 8] * HID;
#pragma unroll
        for (int tn = 0; tn < 8; tn++) {
            int n0 = nb * 128 + wn * 64 + tn * 8 + 2 * tg;
            *(float2*)(C + o0 + n0) = make_float2(acc[tm][tn][0], acc[tm][tn][1]);
            *(float2*)(C + o1 + n0) = make_float2(acc[tm][tn][2], acc[tm][tn][3]);
        }
    }
}

// ---- one-time prep: transpose + tf32-split W [K][N] -> hi/lo [N][K] --------
__global__ void k_wsplit(const float* __restrict__ W, float* __restrict__ hi,
                         float* __restrict__ lo, int K, int N) {
    int idx = blockIdx.x * blockDim.x + threadIdx.x;
    if (idx >= N * K) return;
    int n = idx / K, k = idx % K;
    float v = W[(size_t)k * N + n];
    float h = totf(v);
    hi[idx] = h;
    lo[idx] = totf(v - h);
}

// ---------------- graph preprocessing ---------------------------------------
__global__ void k_init() {
    int i = blockIdx.x * blockDim.x + threadIdx.x;
    if (i < NN) { g_cnt[i] = 0; g_nmask[i] = 1.f; g_rows[i] = 1.f; g_iota[i] = i; }
    if (i == 0) { g_ctr2 = 0; g_ctr3 = 0; }
}

__global__ void k_count(const int* __restrict__ dst) {
    int e = blockIdx.x * blockDim.x + threadIdx.x;
    if (e < EE) atomicAdd(&g_cnt[dst[e]], 1);
}

__global__ void k_scan() {
    __shared__ int part[1024];
    int t = threadIdx.x;
    int base = t * 32;
    int s = 0;
#pragma unroll
    for (int i = 0; i < 32; i++) s += g_cnt[base + i];
    part[t] = s;
    __syncthreads();
    for (int off = 1; off < 1024; off <<= 1) {
        int v = (t >= off) ? part[t - off] : 0;
        __syncthreads();
        part[t] += v;
        __syncthreads();
    }
    int run = (t == 0) ? 0 : part[t - 1];
#pragma unroll
    for (int i = 0; i < 32; i++) {
        int c = g_cnt[base + i];
        g_off[base + i] = run;
        g_cur[base + i] = run;
        run += c;
    }
    if (t == 1023) g_off[NN] = run;
}

__global__ void k_scatter(const int* __restrict__ src, const int* __restrict__ dst) {
    int e = blockIdx.x * blockDim.x + threadIdx.x;
    if (e < EE) {
        int p = atomicAdd(&g_cur[dst[e]], 1);
        g_csr[p] = src[e];
    }
}

__global__ void k_compact(int* __restrict__ ridx, int* __restrict__ ctr) {
    int v = blockIdx.x * blockDim.x + threadIdx.x;
    if (v < NN && g_nmask[v] > 0.f) {
        int p = atomicAdd(ctr, 1);
        ridx[p] = v;
    }
}

// ---------------- GCN pieces -------------------------------------------------
__global__ void k_deg() {
    int v = blockIdx.x * blockDim.x + threadIdx.x;
    if (v >= NN) return;
    if (g_nmask[v] <= 0.f) { g_dinv[v] = 0.f; return; }
    float s = 0.f;
    int e0 = g_off[v], e1 = g_off[v + 1];
    for (int i = e0; i < e1; i++) s += g_nmask[g_csr[i]];
    g_dinv[v] = rsqrtf(s + 1.f);
}

// agg + lrelu + (optional) fused pool-score dot products
__global__ void k_agg(const float* __restrict__ bias, const float* __restrict__ wr,
                      const float* __restrict__ wo, int dopool) {
    __shared__ float s2[8];
    int v = blockIdx.x;
    int c = threadIdx.x;
    float dv = g_dinv[v];
    if (dv == 0.f) return;
    float a0 = 0.f, a1 = 0.f, a2 = 0.f, a3 = 0.f;
    int e0 = g_off[v], e1 = g_off[v + 1];
    for (int i = e0; i < e1; i++) {
        int s = g_csr[i];
        float ds = g_dinv[s];
        if (ds != 0.f) {
            const float* tr = g_t + (size_t)s * HID;
            a0 += ds * tr[c];
            a1 += ds * tr[c + 128];
            a2 += ds * tr[c + 256];
            a3 += ds * tr[c + 384];
        }
    }
    const float* tv = g_t + (size_t)v * HID;
    float dv2 = dv * dv;
    float h0 = lrelu(dv * a0 + dv2 * tv[c]       + bias[c]);
    float h1 = lrelu(dv * a1 + dv2 * tv[c + 128] + bias[c + 128]);
    float h2 = lrelu(dv * a2 + dv2 * tv[c + 256] + bias[c + 256]);
    float h3 = lrelu(dv * a3 + dv2 * tv[c + 384] + bias[c + 384]);
    float* ho = g_h + (size_t)v * HID;
    ho[c] = h0; ho[c + 128] = h1; ho[c + 256] = h2; ho[c + 384] = h3;

    if (dopool) {
        float pr = h0 * wr[c] + h1 * wr[c + 128] + h2 * wr[c + 256] + h3 * wr[c + 384];
        float po = h0 * wo[c] + h1 * wo[c + 128] + h2 * wo[c + 256] + h3 * wo[c + 384];
#pragma unroll
        for (int o = 16; o > 0; o >>= 1) {
            pr += __shfl_down_sync(0xffffffff, pr, o);
            po += __shfl_down_sync(0xffffffff, po, o);
        }
        int wid = c >> 5;
        if ((c & 31) == 0) { s2[wid * 2] = pr; s2[wid * 2 + 1] = po; }
        __syncthreads();
        if (c == 0) {
            g_sr[v] = s2[0] + s2[2] + s2[4] + s2[6];
            g_so[v] = s2[1] + s2[3] + s2[5] + s2[7];
        }
    }
}

__global__ void k_score(const float* __restrict__ br) {
    int v = blockIdx.x * blockDim.x + threadIdx.x;
    if (v >= NN) return;
    if (g_nmask[v] <= 0.f) { g_score[v] = -1e30f; return; }
    float s = 0.f;
    int e0 = g_off[v], e1 = g_off[v + 1];
    for (int i = e0; i < e1; i++) {
        int u = g_csr[i];
        s += g_nmask[u] * g_sr[u];
    }
    g_score[v] = s + br[0] + g_so[v];
}

__global__ void k_topk(int kkeep) {
    __shared__ float v[NPG];
    int g = blockIdx.x, t = threadIdx.x;
    for (int i = t; i < NPG; i += 1024) v[i] = g_score[g * NPG + i];
    __syncthreads();
    for (int ksz = 2; ksz <= NPG; ksz <<= 1) {
        for (int j = ksz >> 1; j > 0; j >>= 1) {
            for (int i = t; i < NPG; i += 1024) {
                int ixj = i ^ j;
                if (ixj > i) {
                    bool up = ((i & ksz) == 0);
                    float a = v[i], b = v[ixj];
                    if (up ? (a > b) : (a < b)) { v[i] = b; v[ixj] = a; }
                }
            }
            __syncthreads();
        }
    }
    float T = v[NPG - kkeep];
    for (int i = t; i < NPG; i += 1024) {
        int node = g * NPG + i;
        float sc = g_score[node];
        float keep = (sc >= T && g_nmask[node] > 0.f) ? 1.f : 0.f;
        g_nmask[node] = keep;
        g_rows[node] = keep * tanhf(sc);
    }
}

// ---------------- readout: two-phase pooling --------------------------------
__global__ void k_pool1() {   // grid = BB*16, block = 512
    int g = blockIdx.x >> 4, ch = blockIdx.x & 15, c = threadIdx.x;
    int n0 = g * NPG + ch * 256;
    float sum = 0.f, mx = -3.4e38f, cnt = 0.f;
    for (int n = 0; n < 256; n++) {
        int node = n0 + n;
        float nm = g_nmask[node];
        if (nm > 0.f) {
            float h = g_h[(size_t)node * HID + c];
            sum += h;
            mx = fmaxf(mx, h);
            cnt += 1.f;
        }
    }
    g_pp_sum[(size_t)blockIdx.x * HID + c] = sum;
    g_pp_max[(size_t)blockIdx.x * HID + c] = mx;
    if (c == 0) g_pp_cnt[blockIdx.x] = cnt;
}

__global__ void k_pool2() {   // grid = BB, block = 512
    __shared__ float scnt;
    int g = blockIdx.x, c = threadIdx.x;
    if (c == 0) {
        float t = 0.f;
        for (int j = 0; j < 16; j++) t += g_pp_cnt[g * 16 + j];
        scnt = t;
    }
    __syncthreads();
    float sum = 0.f, mx = -3.4e38f;
    for (int j = 0; j < 16; j++) {
        sum += g_pp_sum[(size_t)(g * 16 + j) * HID + c];
        mx = fmaxf(mx, g_pp_max[(size_t)(g * 16 + j) * HID + c]);
    }
    g_pool[g * (2 * HID) + c]       = sum / scnt;
    g_pool[g * (2 * HID) + HID + c] = mx;
}

__global__ void k_fc1(const float* __restrict__ w, const float* __restrict__ b) {
    int g = blockIdx.x, o = threadIdx.x;
    const float* gp = g_pool + g * (2 * HID);
    float s = b[o];
    for (int k = 0; k < 2 * HID; k++) s = fmaf(gp[k], w[k * HID + o], s);
    g_fc1o[g * HID + o] = lrelu(s);
}

__global__ void k_fc2(const float* __restrict__ w, const float* __restrict__ b,
                      float* __restrict__ out) {
    int idx = threadIdx.x;
    if (idx >= BB * NCLS) return;
    int g = idx / NCLS, c = idx % NCLS;
    const float* hv = g_fc1o + g * HID;
    float s = b[c];
    for (int k = 0; k < HID; k++) s = fmaf(hv[k], w[k * NCLS + c], s);
    out[idx] = s;
}

// ---------------- launch -----------------------------------------------------
extern "C" void kernel_launch(void* const* d_in, const int* in_sizes, int n_in,
                              void* d_out, int out_size) {
    const float* x     = (const float*)d_in[0];
    const int*   esrc  = (const int*)d_in[1];
    const int*   edst  = (const int*)d_in[2];
    const float* W1    = (const float*)d_in[3];
    const float* b1    = (const float*)d_in[4];
    const float* p1wr  = (const float*)d_in[5];
    const float* p1br  = (const float*)d_in[6];
    const float* p1wo  = (const float*)d_in[7];
    const float* W2    = (const float*)d_in[8];
    const float* b2    = (const float*)d_in[9];
    const float* p2wr  = (const float*)d_in[10];
    const float* p2br  = (const float*)d_in[11];
    const float* p2wo  = (const float*)d_in[12];
    const float* W3    = (const float*)d_in[13];
    const float* b3    = (const float*)d_in[14];
    const float* fc1w  = (const float*)d_in[15];
    const float* fc1b  = (const float*)d_in[16];
    const float* fc2w  = (const float*)d_in[17];
    const float* fc2b  = (const float*)d_in[18];
    float* out = (float*)d_out;

    float* dT;     cudaGetSymbolAddress((void**)&dT, g_t);
    float* dH;     cudaGetSymbolAddress((void**)&dH, g_h);
    float* dRS;    cudaGetSymbolAddress((void**)&dRS, g_rows);
    float* dW1hi;  cudaGetSymbolAddress((void**)&dW1hi, g_w1t_hi);
    float* dW1lo;  cudaGetSymbolAddress((void**)&dW1lo, g_w1t_lo);
    float* dW2hi;  cudaGetSymbolAddress((void**)&dW2hi, g_w2t_hi);
    float* dW2lo;  cudaGetSymbolAddress((void**)&dW2lo, g_w2t_lo);
    float* dW3hi;  cudaGetSymbolAddress((void**)&dW3hi, g_w3t_hi);
    float* dW3lo;  cudaGetSymbolAddress((void**)&dW3lo, g_w3t_lo);
    int*   dIota;  cudaGetSymbolAddress((void**)&dIota, g_iota);
    int*   dR2;    cudaGetSymbolAddress((void**)&dR2, g_ridx2);
    int*   dR3;    cudaGetSymbolAddress((void**)&dR3, g_ridx3);
    int*   dC2;    cudaGetSymbolAddress((void**)&dC2, g_ctr2);
    int*   dC3;    cudaGetSymbolAddress((void**)&dC3, g_ctr3);

    static int cfg_done = 0;
    if (!cfg_done) {
        cudaFuncSetAttribute(mma_gemm, cudaFuncAttributeMaxDynamicSharedMemorySize, SM_BYTES);
        cfg_done = 1;
    }

    // order chosen so mma_gemm (layer 1) is launch idx 3 -> gets profiled
    k_init<<<NN / 256, 256>>>();
    k_wsplit<<<(HID * INC) / 256, 256>>>(W1, dW1hi, dW1lo, INC, HID);
    k_count<<<EE / 256, 256>>>(edst);
    mma_gemm<<<dim3(HID / 128, NN / 128), 256, SM_BYTES>>>(x, dW1hi, dW1lo, dRS, dIota, dT, INC);
    k_scan<<<1, 1024>>>();
    k_scatter<<<EE / 256, 256>>>(esrc, edst);
    k_wsplit<<<(HID * HID) / 256, 256>>>(W2, dW2hi, dW2lo, HID, HID);
    k_wsplit<<<(HID * HID) / 256, 256>>>(W3, dW3hi, dW3lo, HID, HID);

    // ---- layer 1 epilogue + pool 1 ----
    k_deg<<<NN / 256, 256>>>();
    k_agg<<<NN, 128>>>(b1, p1wr, p1wo, 1);
    k_score<<<NN / 256, 256>>>(p1br);
    k_topk<<<BB, 1024>>>(K1);
    k_compact<<<NN / 256, 256>>>(dR2, dC2);

    // ---- layer 2 ----
    mma_gemm<<<dim3(HID / 128, NACT2 / 128), 256, SM_BYTES>>>(dH, dW2hi, dW2lo, dRS, dR2, dT, HID);
    k_deg<<<NN / 256, 256>>>();
    k_agg<<<NN, 128>>>(b2, p2wr, p2wo, 1);
    k_score<<<NN / 256, 256>>>(p2br);
    k_topk<<<BB, 1024>>>(K2);
    k_compact<<<NN / 256, 256>>>(dR3, dC3);

    // ---- layer 3 ----
    mma_gemm<<<dim3(HID / 128, NACT3 / 128), 256, SM_BYTES>>>(dH, dW3hi, dW3lo, dRS, dR3, dT, HID);
    k_deg<<<NN / 256, 256>>>();
    k_agg<<<NN, 128>>>(b3, (const float*)0, (const float*)0, 0);

    // ---- readout ----
    k_pool1<<<BB * 16, HID>>>();
    k_pool2<<<BB, HID>>>();
    k_fc1<<<BB, HID>>>(fc1w, fc1b);
    k_fc2<<<1, 32>>>(fc2w, fc2b, out);
}